// round 2
// baseline (speedup 1.0000x reference)
#include <cuda_runtime.h>
#include <cuda_bf16.h>
#include <cstdint>

#define NNODES 100000
#define NEDGES 600000
#define DH 128
#define SCAN_CHUNK 1024
#define NSCAN_BLOCKS ((NNODES + SCAN_CHUNK - 1) / SCAN_CHUNK)   // 98

// ---------------- scratch (static device memory; no allocations) -------------
__device__ float g_h[(size_t)NNODES * DH];     // 51.2 MB
__device__ float g_agg[(size_t)NNODES * DH];   // 51.2 MB
__device__ float g_dinv[NNODES];
__device__ int   g_deg[NNODES];
__device__ int   g_start[NNODES + 1];
__device__ int   g_cursor[NNODES];
__device__ int   g_src[NEDGES];
__device__ int   g_blocksums[NSCAN_BLOCKS];
__device__ float g_colsum[DH];
__device__ float g_colsq[DH];
__device__ float g_scale[DH];
__device__ float g_shift[DH];

// ---------------- init: zero deg + column stats ------------------------------
__global__ void k_init() {
    int i = blockIdx.x * blockDim.x + threadIdx.x;
    if (i < NNODES) g_deg[i] = 0;
    if (i < DH) { g_colsum[i] = 0.f; g_colsq[i] = 0.f; }
}

// ---------------- count incoming degree (dst side only, per reference) -------
__global__ void k_count(const int* __restrict__ ei) {
    int e = blockIdx.x * blockDim.x + threadIdx.x;
    if (e >= NEDGES) return;
    int dst = ei[NEDGES + e];
    atomicAdd(&g_deg[dst], 1);
}

// ---------------- block-wise exclusive scan of deg ---------------------------
__global__ void k_scan1() {
    __shared__ int s[SCAN_CHUNK];
    int i = blockIdx.x * SCAN_CHUNK + threadIdx.x;
    int v = (i < NNODES) ? g_deg[i] : 0;
    s[threadIdx.x] = v;
    __syncthreads();
    for (int off = 1; off < SCAN_CHUNK; off <<= 1) {
        int t = (threadIdx.x >= off) ? s[threadIdx.x - off] : 0;
        __syncthreads();
        s[threadIdx.x] += t;
        __syncthreads();
    }
    if (i < NNODES) g_start[i] = s[threadIdx.x] - v;   // exclusive within block
    if (threadIdx.x == SCAN_CHUNK - 1) g_blocksums[blockIdx.x] = s[SCAN_CHUNK - 1];
}

__global__ void k_scan2() {
    // tiny: sequential exclusive scan of 98 block sums
    int acc = 0;
    for (int b = 0; b < NSCAN_BLOCKS; b++) {
        int t = g_blocksums[b];
        g_blocksums[b] = acc;
        acc += t;
    }
}

__global__ void k_scan3() {
    int i = blockIdx.x * blockDim.x + threadIdx.x;
    if (i < NNODES) {
        int st = g_start[i] + g_blocksums[i / SCAN_CHUNK];
        g_start[i] = st;
        g_cursor[i] = st;
        g_dinv[i] = rsqrtf((float)(g_deg[i] + 1));     // +1 self loop
    }
    if (i == 0) g_start[NNODES] = NEDGES;
}

// ---------------- scatter edges into CSR (by dst) ----------------------------
__global__ void k_buildcsr(const int* __restrict__ ei) {
    int e = blockIdx.x * blockDim.x + threadIdx.x;
    if (e >= NEDGES) return;
    int src = ei[e];
    int dst = ei[NEDGES + e];
    int pos = atomicAdd(&g_cursor[dst], 1);
    g_src[pos] = src;
}

// ---------------- SGEMM: C[M,128] = A[M,128] @ B[128,128] --------------------
// classic 128x128x8 tile, 256 threads, 8x8 microtile per thread
__global__ void k_gemm(const float* __restrict__ A, const float* __restrict__ B,
                       float* __restrict__ C, int M) {
    __shared__ float As[8][128];
    __shared__ float Bs[8][128];
    int tid = threadIdx.x;
    int ty = tid / 16, tx = tid % 16;
    int rowBase = blockIdx.x * 128;

    float acc[8][8];
#pragma unroll
    for (int i = 0; i < 8; i++)
#pragma unroll
        for (int j = 0; j < 8; j++) acc[i][j] = 0.f;

    int aRow = tid >> 1;            // 0..127
    int aCol = (tid & 1) * 4;       // 0 or 4
    int bRow = tid >> 5;            // 0..7
    int bCol = (tid & 31) * 4;      // 0..124

    for (int k0 = 0; k0 < 128; k0 += 8) {
        int gr = rowBase + aRow;
        float4 av = make_float4(0.f, 0.f, 0.f, 0.f);
        if (gr < M) av = *(const float4*)(A + (size_t)gr * 128 + k0 + aCol);
        As[aCol + 0][aRow] = av.x;
        As[aCol + 1][aRow] = av.y;
        As[aCol + 2][aRow] = av.z;
        As[aCol + 3][aRow] = av.w;
        float4 bv = *(const float4*)(B + (size_t)(k0 + bRow) * 128 + bCol);
        *(float4*)&Bs[bRow][bCol] = bv;
        __syncthreads();
#pragma unroll
        for (int k = 0; k < 8; k++) {
            float a[8], b[8];
#pragma unroll
            for (int i = 0; i < 8; i++) a[i] = As[k][ty * 8 + i];
#pragma unroll
            for (int j = 0; j < 8; j++) b[j] = Bs[k][tx * 8 + j];
#pragma unroll
            for (int i = 0; i < 8; i++)
#pragma unroll
                for (int j = 0; j < 8; j++) acc[i][j] = fmaf(a[i], b[j], acc[i][j]);
        }
        __syncthreads();
    }
#pragma unroll
    for (int i = 0; i < 8; i++) {
        int gr = rowBase + ty * 8 + i;
        if (gr >= M) continue;
        float* cp = C + (size_t)gr * 128 + tx * 8;
        *(float4*)(cp)     = make_float4(acc[i][0], acc[i][1], acc[i][2], acc[i][3]);
        *(float4*)(cp + 4) = make_float4(acc[i][4], acc[i][5], acc[i][6], acc[i][7]);
    }
}

// ---------------- gather-based GCN aggregation: warp per node ----------------
// out[n] = dinv[n] * ( h[n]*dinv[n] + sum_{s in in(n)} h[s]*dinv[s] ) + bias
__global__ void k_agg(const float* __restrict__ h, const float* __restrict__ bias,
                      float* __restrict__ out) {
    int warp = (blockIdx.x * blockDim.x + threadIdx.x) >> 5;
    int lane = threadIdx.x & 31;
    if (warp >= NNODES) return;
    int n = warp;
    float di = g_dinv[n];
    float4 acc = ((const float4*)(h + (size_t)n * DH))[lane];
    acc.x *= di; acc.y *= di; acc.z *= di; acc.w *= di;
    int beg = g_start[n], end = g_start[n + 1];
    for (int idx = beg; idx < end; idx++) {
        int s = g_src[idx];
        float w = g_dinv[s];
        float4 v = ((const float4*)(h + (size_t)s * DH))[lane];
        acc.x = fmaf(v.x, w, acc.x);
        acc.y = fmaf(v.y, w, acc.y);
        acc.z = fmaf(v.z, w, acc.z);
        acc.w = fmaf(v.w, w, acc.w);
    }
    acc.x *= di; acc.y *= di; acc.z *= di; acc.w *= di;
    float4 bv = ((const float4*)bias)[lane];
    acc.x += bv.x; acc.y += bv.y; acc.z += bv.z; acc.w += bv.w;
    ((float4*)(out + (size_t)n * DH))[lane] = acc;
}

// ---------------- per-column sum / sumsq over g_agg --------------------------
__global__ void k_colstats() {
    int t = threadIdx.x;   // 128 threads: one column each
    float sum = 0.f, sq = 0.f;
    for (int r = blockIdx.x; r < NNODES; r += gridDim.x) {
        float v = g_agg[(size_t)r * DH + t];
        sum += v;
        sq = fmaf(v, v, sq);
    }
    atomicAdd(&g_colsum[t], sum);
    atomicAdd(&g_colsq[t], sq);
}

__global__ void k_bnstats(const float* __restrict__ gamma, const float* __restrict__ beta) {
    int t = threadIdx.x;
    float mean = g_colsum[t] * (1.0f / NNODES);
    float var = g_colsq[t] * (1.0f / NNODES) - mean * mean;
    float inv = rsqrtf(var + 1e-5f);
    float sc = gamma[t] * inv;
    g_scale[t] = sc;
    g_shift[t] = beta[t] - mean * sc;
}

// ---------------- BN apply + ReLU: g_agg -> g_h ------------------------------
__global__ void k_bnrelu() {
    int idx = blockIdx.x * blockDim.x + threadIdx.x;   // over N*32 float4s
    if (idx >= NNODES * (DH / 4)) return;
    int c = (idx & 31) * 4;
    float4 v = ((const float4*)g_agg)[idx];
    v.x = fmaxf(fmaf(v.x, g_scale[c + 0], g_shift[c + 0]), 0.f);
    v.y = fmaxf(fmaf(v.y, g_scale[c + 1], g_shift[c + 1]), 0.f);
    v.z = fmaxf(fmaf(v.z, g_scale[c + 2], g_shift[c + 2]), 0.f);
    v.w = fmaxf(fmaf(v.w, g_scale[c + 3], g_shift[c + 3]), 0.f);
    ((float4*)g_h)[idx] = v;
}

// ---------------- launch -----------------------------------------------------
extern "C" void kernel_launch(void* const* d_in, const int* in_sizes, int n_in,
                              void* d_out, int out_size) {
    const float* x     = (const float*)d_in[0];
    const int*   ei    = (const int*)d_in[1];      // int32! (JAX default, no x64)
    const float* W1    = (const float*)d_in[2];
    const float* b1    = (const float*)d_in[3];
    const float* gamma = (const float*)d_in[4];
    const float* beta  = (const float*)d_in[5];
    const float* W2    = (const float*)d_in[6];
    const float* b2    = (const float*)d_in[7];
    float*       out   = (float*)d_out;

    float* h   = nullptr; cudaGetSymbolAddress((void**)&h,   g_h);
    float* agg = nullptr; cudaGetSymbolAddress((void**)&agg, g_agg);

    // graph structure (recomputed every call; deterministic)
    k_init<<<(NNODES + 255) / 256, 256>>>();
    k_count<<<(NEDGES + 255) / 256, 256>>>(ei);
    k_scan1<<<NSCAN_BLOCKS, SCAN_CHUNK>>>();
    k_scan2<<<1, 1>>>();
    k_scan3<<<(NNODES + 255) / 256, 256>>>();
    k_buildcsr<<<(NEDGES + 255) / 256, 256>>>(ei);

    // layer 1: GEMM -> aggregate -> BN stats -> BN+ReLU
    k_gemm<<<(NNODES + 127) / 128, 256>>>(x, W1, h, NNODES);
    k_agg<<<(NNODES * 32 + 255) / 256, 256>>>(h, b1, agg);
    k_colstats<<<512, DH>>>();
    k_bnstats<<<1, DH>>>(gamma, beta);
    k_bnrelu<<<(NNODES * 32 + 255) / 256, 256>>>();

    // layer 2: GEMM -> aggregate -> d_out
    k_gemm<<<(NNODES + 127) / 128, 256>>>(h, W2, agg, NNODES);
    k_agg<<<(NNODES * 32 + 255) / 256, 256>>>(agg, b2, out);
}

// round 5
// speedup vs baseline: 3.0013x; 3.0013x over previous
#include <cuda_runtime.h>
#include <cuda_bf16.h>
#include <cstdint>

#define NNODES 100000
#define NEDGES 600000
#define DH 128
#define SCAN_CHUNK 1024
#define NSCAN_BLOCKS ((NNODES + SCAN_CHUNK - 1) / SCAN_CHUNK)   // 98
#define NREP 32   // replicated column-stat accumulators

// ---------------- scratch (static device memory; no allocations) -------------
__device__ float g_h[(size_t)NNODES * DH];     // 51.2 MB
__device__ float g_agg[(size_t)NNODES * DH];   // 51.2 MB
__device__ float g_dinv[NNODES];
__device__ int   g_deg[NNODES];
__device__ int   g_start[NNODES + 1];
__device__ int   g_cursor[NNODES];
__device__ int   g_src[NEDGES];
__device__ int   g_blocksums[NSCAN_BLOCKS];
__device__ float g_colsum_r[NREP][DH];
__device__ float g_colsq_r[NREP][DH];
__device__ float g_scale[DH];
__device__ float g_shift[DH];

// ---------------- helpers ----------------------------------------------------
__device__ __forceinline__ uint32_t f2tf32(float f) {
    uint32_t r;
    asm("cvt.rna.tf32.f32 %0, %1;" : "=r"(r) : "f"(f));
    return r;
}

__device__ __forceinline__ void mma_tf32(float* c, const uint32_t* a, const uint32_t* b) {
    asm volatile("mma.sync.aligned.m16n8k8.row.col.f32.tf32.tf32.f32 "
        "{%0,%1,%2,%3}, {%4,%5,%6,%7}, {%8,%9}, {%0,%1,%2,%3};"
        : "+f"(c[0]), "+f"(c[1]), "+f"(c[2]), "+f"(c[3])
        : "r"(a[0]), "r"(a[1]), "r"(a[2]), "r"(a[3]), "r"(b[0]), "r"(b[1]));
}

// ---------------- init: zero deg + replicated column stats --------------------
__global__ void k_init() {
    int i = blockIdx.x * blockDim.x + threadIdx.x;
    if (i < NNODES) g_deg[i] = 0;
    if (i < NREP * DH) {
        ((float*)g_colsum_r)[i] = 0.f;
        ((float*)g_colsq_r)[i] = 0.f;
    }
}

// ---------------- count incoming degree (dst side) ----------------------------
__global__ void k_count(const int* __restrict__ ei) {
    int e = blockIdx.x * blockDim.x + threadIdx.x;
    if (e >= NEDGES) return;
    atomicAdd(&g_deg[ei[NEDGES + e]], 1);
}

// ---------------- block-wise exclusive scan of deg ---------------------------
__global__ void k_scan1() {
    __shared__ int s[SCAN_CHUNK];
    int i = blockIdx.x * SCAN_CHUNK + threadIdx.x;
    int v = (i < NNODES) ? g_deg[i] : 0;
    s[threadIdx.x] = v;
    __syncthreads();
    for (int off = 1; off < SCAN_CHUNK; off <<= 1) {
        int t = (threadIdx.x >= off) ? s[threadIdx.x - off] : 0;
        __syncthreads();
        s[threadIdx.x] += t;
        __syncthreads();
    }
    if (i < NNODES) g_start[i] = s[threadIdx.x] - v;
    if (threadIdx.x == SCAN_CHUNK - 1) g_blocksums[blockIdx.x] = s[SCAN_CHUNK - 1];
}

__global__ void k_scan2() {
    // parallel Hillis-Steele over NSCAN_BLOCKS (98) values, 128 threads
    __shared__ int s[128];
    int t = threadIdx.x;
    int v = (t < NSCAN_BLOCKS) ? g_blocksums[t] : 0;
    s[t] = v;
    __syncthreads();
    for (int off = 1; off < 128; off <<= 1) {
        int u = (t >= off) ? s[t - off] : 0;
        __syncthreads();
        s[t] += u;
        __syncthreads();
    }
    if (t < NSCAN_BLOCKS) g_blocksums[t] = s[t] - v;   // exclusive
}

__global__ void k_scan3() {
    int i = blockIdx.x * blockDim.x + threadIdx.x;
    if (i < NNODES) {
        int st = g_start[i] + g_blocksums[i / SCAN_CHUNK];
        g_start[i] = st;
        g_cursor[i] = st;
        g_dinv[i] = rsqrtf((float)(g_deg[i] + 1));
    }
    if (i == 0) g_start[NNODES] = NEDGES;
}

// ---------------- scatter edges into CSR (by dst) ----------------------------
__global__ void k_buildcsr(const int* __restrict__ ei) {
    int e = blockIdx.x * blockDim.x + threadIdx.x;
    if (e >= NEDGES) return;
    int src = ei[e];
    int dst = ei[NEDGES + e];
    int pos = atomicAdd(&g_cursor[dst], 1);
    g_src[pos] = src;
}

// ---------------- TF32 tensor-core GEMM: C[M,128] = A[M,128] @ B[128,128] ----
// 128x128 block tile, 256 threads = 8 warps in 4(M)x2(N); warp tile 32x64.
// mma m16n8k8 tf32. FUSE_BN: apply y = relu(a*scale + shift) to A on load.
#define AS_STRIDE 20
#define BS_STRIDE 136
template <bool FUSE_BN>
__global__ void __launch_bounds__(256, 2)
k_gemm(const float* __restrict__ A, const float* __restrict__ B,
       float* __restrict__ C, int M) {
    __shared__ uint32_t As[128][AS_STRIDE];   // [m][k], k-chunk = 16
    __shared__ uint32_t Bs[16][BS_STRIDE];    // [k][n]

    int tid = threadIdx.x;
    int lane = tid & 31;
    int warp = tid >> 5;
    int gid = lane >> 2;     // 0..7
    int tig = lane & 3;      // 0..3
    int wm = warp & 3;       // M warp 0..3
    int wn = warp >> 2;      // N warp 0..1
    int rowBase = blockIdx.x * 128;

    float acc[2][8][4];
#pragma unroll
    for (int i = 0; i < 2; i++)
#pragma unroll
        for (int j = 0; j < 8; j++)
#pragma unroll
            for (int q = 0; q < 4; q++) acc[i][j][q] = 0.f;

    // global load mapping
    int aRow = tid >> 1;               // 0..127
    int aCol = (tid & 1) * 8;          // 0 or 8
    int bRow = tid >> 4;               // 0..15
    int bCol = (tid & 15) * 8;         // 0..120

    for (int k0 = 0; k0 < 128; k0 += 16) {
        // --- A tile: 128 x 16 ---
        {
            int gr = rowBase + aRow;
            float4 v0 = make_float4(0.f, 0.f, 0.f, 0.f), v1 = v0;
            if (gr < M) {
                const float* ap = A + (size_t)gr * 128 + k0 + aCol;
                v0 = *(const float4*)(ap);
                v1 = *(const float4*)(ap + 4);
            }
            if (FUSE_BN) {
                int c = k0 + aCol;
                float4 sc0 = *(const float4*)&g_scale[c];
                float4 sc1 = *(const float4*)&g_scale[c + 4];
                float4 sh0 = *(const float4*)&g_shift[c];
                float4 sh1 = *(const float4*)&g_shift[c + 4];
                v0.x = fmaxf(fmaf(v0.x, sc0.x, sh0.x), 0.f);
                v0.y = fmaxf(fmaf(v0.y, sc0.y, sh0.y), 0.f);
                v0.z = fmaxf(fmaf(v0.z, sc0.z, sh0.z), 0.f);
                v0.w = fmaxf(fmaf(v0.w, sc0.w, sh0.w), 0.f);
                v1.x = fmaxf(fmaf(v1.x, sc1.x, sh1.x), 0.f);
                v1.y = fmaxf(fmaf(v1.y, sc1.y, sh1.y), 0.f);
                v1.z = fmaxf(fmaf(v1.z, sc1.z, sh1.z), 0.f);
                v1.w = fmaxf(fmaf(v1.w, sc1.w, sh1.w), 0.f);
            }
            uint4 t0 = make_uint4(f2tf32(v0.x), f2tf32(v0.y), f2tf32(v0.z), f2tf32(v0.w));
            uint4 t1 = make_uint4(f2tf32(v1.x), f2tf32(v1.y), f2tf32(v1.z), f2tf32(v1.w));
            *(uint4*)&As[aRow][aCol] = t0;
            *(uint4*)&As[aRow][aCol + 4] = t1;
        }
        // --- B tile: 16 x 128 ---
        {
            const float* bp = B + (size_t)(k0 + bRow) * 128 + bCol;
            float4 v0 = *(const float4*)(bp);
            float4 v1 = *(const float4*)(bp + 4);
            uint4 t0 = make_uint4(f2tf32(v0.x), f2tf32(v0.y), f2tf32(v0.z), f2tf32(v0.w));
            uint4 t1 = make_uint4(f2tf32(v1.x), f2tf32(v1.y), f2tf32(v1.z), f2tf32(v1.w));
            *(uint4*)&Bs[bRow][bCol] = t0;
            *(uint4*)&Bs[bRow][bCol + 4] = t1;
        }
        __syncthreads();

#pragma unroll
        for (int ks = 0; ks < 16; ks += 8) {
            uint32_t a[2][4], b[8][2];
#pragma unroll
            for (int i = 0; i < 2; i++) {
                int mb = wm * 32 + i * 16;
                a[i][0] = As[mb + gid][ks + tig];
                a[i][1] = As[mb + gid + 8][ks + tig];
                a[i][2] = As[mb + gid][ks + tig + 4];
                a[i][3] = As[mb + gid + 8][ks + tig + 4];
            }
#pragma unroll
            for (int j = 0; j < 8; j++) {
                int nb = wn * 64 + j * 8;
                b[j][0] = Bs[ks + tig][nb + gid];
                b[j][1] = Bs[ks + tig + 4][nb + gid];
            }
#pragma unroll
            for (int i = 0; i < 2; i++)
#pragma unroll
                for (int j = 0; j < 8; j++) mma_tf32(acc[i][j], a[i], b[j]);
        }
        __syncthreads();
    }

    // epilogue
#pragma unroll
    for (int i = 0; i < 2; i++) {
        int r0 = rowBase + wm * 32 + i * 16 + gid;
        int r1 = r0 + 8;
#pragma unroll
        for (int j = 0; j < 8; j++) {
            int col = wn * 64 + j * 8 + tig * 2;
            if (r0 < M) *(float2*)(C + (size_t)r0 * 128 + col) = make_float2(acc[i][j][0], acc[i][j][1]);
            if (r1 < M) *(float2*)(C + (size_t)r1 * 128 + col) = make_float2(acc[i][j][2], acc[i][j][3]);
        }
    }
}

// ---------------- gather aggregation: warp per node --------------------------
// out[n] = dinv[n]*( h[n]*dinv[n] + sum_{s in in(n)} h[s]*dinv[s] ) + bias
// STATS: also accumulate per-column sum / sumsq of the output (BN input).
template <bool STATS>
__global__ void k_agg(const float* __restrict__ h, const float* __restrict__ bias,
                      float* __restrict__ out) {
    __shared__ float s_sum[8][DH];
    __shared__ float s_sq[8][DH];
    int warp = threadIdx.x >> 5;
    int lane = threadIdx.x & 31;
    int n = blockIdx.x * 8 + warp;
    float4 acc = make_float4(0.f, 0.f, 0.f, 0.f);
    if (n < NNODES) {
        float di = g_dinv[n];
        acc = ((const float4*)(h + (size_t)n * DH))[lane];
        acc.x *= di; acc.y *= di; acc.z *= di; acc.w *= di;
        int beg = g_start[n], end = g_start[n + 1];
        for (int idx = beg; idx < end; idx++) {
            int s = g_src[idx];
            float w = g_dinv[s];
            float4 v = ((const float4*)(h + (size_t)s * DH))[lane];
            acc.x = fmaf(v.x, w, acc.x);
            acc.y = fmaf(v.y, w, acc.y);
            acc.z = fmaf(v.z, w, acc.z);
            acc.w = fmaf(v.w, w, acc.w);
        }
        float4 bv = ((const float4*)bias)[lane];
        acc.x = fmaf(acc.x, di, bv.x);
        acc.y = fmaf(acc.y, di, bv.y);
        acc.z = fmaf(acc.z, di, bv.z);
        acc.w = fmaf(acc.w, di, bv.w);
        ((float4*)(out + (size_t)n * DH))[lane] = acc;
    }
    if (STATS) {
        int c = lane * 4;
        s_sum[warp][c + 0] = acc.x; s_sum[warp][c + 1] = acc.y;
        s_sum[warp][c + 2] = acc.z; s_sum[warp][c + 3] = acc.w;
        s_sq[warp][c + 0] = acc.x * acc.x; s_sq[warp][c + 1] = acc.y * acc.y;
        s_sq[warp][c + 2] = acc.z * acc.z; s_sq[warp][c + 3] = acc.w * acc.w;
        __syncthreads();
        int t = threadIdx.x;
        int rep = blockIdx.x & (NREP - 1);
        if (t < DH) {
            float s = 0.f;
#pragma unroll
            for (int w = 0; w < 8; w++) s += s_sum[w][t];
            atomicAdd(&g_colsum_r[rep][t], s);
        } else {
            int c2 = t - DH;
            float s = 0.f;
#pragma unroll
            for (int w = 0; w < 8; w++) s += s_sq[w][c2];
            atomicAdd(&g_colsq_r[rep][c2], s);
        }
    }
}

// ---------------- BN stats: reduce replicas -> scale/shift --------------------
__global__ void k_bnstats(const float* __restrict__ gamma, const float* __restrict__ beta) {
    int t = threadIdx.x;
    float sum = 0.f, sq = 0.f;
#pragma unroll
    for (int r = 0; r < NREP; r++) { sum += g_colsum_r[r][t]; sq += g_colsq_r[r][t]; }
    float mean = sum * (1.0f / NNODES);
    float var = sq * (1.0f / NNODES) - mean * mean;
    float inv = rsqrtf(var + 1e-5f);
    float sc = gamma[t] * inv;
    g_scale[t] = sc;
    g_shift[t] = beta[t] - mean * sc;
}

// ---------------- launch -----------------------------------------------------
extern "C" void kernel_launch(void* const* d_in, const int* in_sizes, int n_in,
                              void* d_out, int out_size) {
    const float* x     = (const float*)d_in[0];
    const int*   ei    = (const int*)d_in[1];
    const float* W1    = (const float*)d_in[2];
    const float* b1    = (const float*)d_in[3];
    const float* gamma = (const float*)d_in[4];
    const float* beta  = (const float*)d_in[5];
    const float* W2    = (const float*)d_in[6];
    const float* b2    = (const float*)d_in[7];
    float*       out   = (float*)d_out;

    float* h   = nullptr; cudaGetSymbolAddress((void**)&h,   g_h);
    float* agg = nullptr; cudaGetSymbolAddress((void**)&agg, g_agg);

    // graph structure
    k_init<<<(NNODES + 255) / 256, 256>>>();
    k_count<<<(NEDGES + 255) / 256, 256>>>(ei);
    k_scan1<<<NSCAN_BLOCKS, SCAN_CHUNK>>>();
    k_scan2<<<1, 128>>>();
    k_scan3<<<(NNODES + 255) / 256, 256>>>();
    k_buildcsr<<<(NEDGES + 255) / 256, 256>>>(ei);

    // layer 1: GEMM(tf32) -> aggregate(+colstats) -> BN params
    k_gemm<false><<<(NNODES + 127) / 128, 256>>>(x, W1, h, NNODES);
    k_agg<true><<<(NNODES + 7) / 8, 256>>>(h, b1, agg);
    k_bnstats<<<1, DH>>>(gamma, beta);

    // layer 2: GEMM(tf32, fused BN+ReLU on A) -> aggregate -> d_out
    k_gemm<true><<<(NNODES + 127) / 128, 256>>>(agg, W2, h, NNODES);
    k_agg<false><<<(NNODES + 7) / 8, 256>>>(h, b2, out);
}

// round 6
// speedup vs baseline: 3.0399x; 1.0129x over previous
#include <cuda_runtime.h>
#include <cuda_bf16.h>
#include <cstdint>

#define NNODES 100000
#define NEDGES 600000
#define DH 128
#define SCAN_CHUNK 1024
#define NSCAN_BLOCKS ((NNODES + SCAN_CHUNK - 1) / SCAN_CHUNK)   // 98
#define NREP 32   // replicated column-stat accumulators

// ---------------- scratch (static device memory; no allocations) -------------
__device__ float g_h[(size_t)NNODES * DH];     // 51.2 MB
__device__ float g_agg[(size_t)NNODES * DH];   // 51.2 MB
__device__ float g_dinv[NNODES];
__device__ int   g_deg[NNODES];
__device__ int   g_start[NNODES + 1];
__device__ int   g_cursor[NNODES];
__device__ int   g_src[NEDGES];
__device__ int   g_blocksums[NSCAN_BLOCKS];
__device__ float g_colsum_r[NREP][DH];
__device__ float g_colsq_r[NREP][DH];
__device__ float g_scale[DH];
__device__ float g_shift[DH];

// ---------------- helpers ----------------------------------------------------
__device__ __forceinline__ uint32_t f2tf32(float f) {
    uint32_t r;
    asm("cvt.rna.tf32.f32 %0, %1;" : "=r"(r) : "f"(f));
    return r;
}

__device__ __forceinline__ void mma_tf32(float* c, const uint32_t* a, const uint32_t* b) {
    asm volatile("mma.sync.aligned.m16n8k8.row.col.f32.tf32.tf32.f32 "
        "{%0,%1,%2,%3}, {%4,%5,%6,%7}, {%8,%9}, {%0,%1,%2,%3};"
        : "+f"(c[0]), "+f"(c[1]), "+f"(c[2]), "+f"(c[3])
        : "r"(a[0]), "r"(a[1]), "r"(a[2]), "r"(a[3]), "r"(b[0]), "r"(b[1]));
}

// ---------------- init: zero deg + replicated column stats --------------------
__global__ void k_init() {
    int i = blockIdx.x * blockDim.x + threadIdx.x;
    if (i < NNODES) g_deg[i] = 0;
    if (i < NREP * DH) {
        ((float*)g_colsum_r)[i] = 0.f;
        ((float*)g_colsq_r)[i] = 0.f;
    }
}

// ---------------- count incoming degree (dst side) ----------------------------
__global__ void k_count(const int* __restrict__ ei) {
    int e4 = blockIdx.x * blockDim.x + threadIdx.x;
    if (e4 * 4 >= NEDGES) return;
    int4 d = ((const int4*)(ei + NEDGES))[e4];
    atomicAdd(&g_deg[d.x], 1);
    atomicAdd(&g_deg[d.y], 1);
    atomicAdd(&g_deg[d.z], 1);
    atomicAdd(&g_deg[d.w], 1);
}

// ---------------- block-wise inclusive scan of deg (per 1024-chunk) ----------
__global__ void k_scan1() {
    __shared__ int s[SCAN_CHUNK];
    int i = blockIdx.x * SCAN_CHUNK + threadIdx.x;
    int v = (i < NNODES) ? g_deg[i] : 0;
    s[threadIdx.x] = v;
    __syncthreads();
    for (int off = 1; off < SCAN_CHUNK; off <<= 1) {
        int t = (threadIdx.x >= off) ? s[threadIdx.x - off] : 0;
        __syncthreads();
        s[threadIdx.x] += t;
        __syncthreads();
    }
    if (i < NNODES) g_start[i] = s[threadIdx.x] - v;   // exclusive within chunk
    if (threadIdx.x == SCAN_CHUNK - 1) g_blocksums[blockIdx.x] = s[SCAN_CHUNK - 1];
}

// ---------------- finalize offsets: chunk-sum scan done in-block --------------
__global__ void k_scan3() {
    __shared__ int excl[128];
    int t = threadIdx.x;
    // every block scans the 98 chunk sums itself (cheap) -> no separate kernel
    if (t < 128) {
        int v = (t < NSCAN_BLOCKS) ? g_blocksums[t] : 0;
        excl[t] = v;
    }
    __syncthreads();
    if (t < 128) {
        for (int off = 1; off < 128; off <<= 1) {
            int u = (t >= off) ? excl[t - off] : 0;
            __syncthreads();
            excl[t] += u;
            __syncthreads();
        }
        int v = (t < NSCAN_BLOCKS) ? g_blocksums[t] : 0;
        excl[t] -= v;   // exclusive
    } else {
        for (int off = 1; off < 128; off <<= 1) { __syncthreads(); __syncthreads(); }
    }
    __syncthreads();
    int i = blockIdx.x * blockDim.x + t;
    if (i < NNODES) {
        int st = g_start[i] + excl[i >> 10];
        g_start[i] = st;
        g_cursor[i] = st;
        g_dinv[i] = rsqrtf((float)(g_deg[i] + 1));
    }
    if (i == 0) g_start[NNODES] = NEDGES;
}

// ---------------- scatter edges into CSR (by dst) ----------------------------
__global__ void k_buildcsr(const int* __restrict__ ei) {
    int e = blockIdx.x * blockDim.x + threadIdx.x;
    if (e >= NEDGES) return;
    int src = ei[e];
    int dst = ei[NEDGES + e];
    int pos = atomicAdd(&g_cursor[dst], 1);
    g_src[pos] = src;
}

// ---------------- TF32 tensor-core GEMM: C[M,128] = A[M,128] @ B[128,128] ----
// 128x128 block tile, 256 threads = 8 warps in 4(M)x2(N); warp tile 32x64.
// Double-buffered smem pipeline: prefetch regs -> compute -> store -> 1 sync.
#define AS_STRIDE 20
#define BS_STRIDE 136

template <bool FUSE_BN>
__device__ __forceinline__ void gemm_load_regs(
    const float* __restrict__ A, const float* __restrict__ B, int M,
    int rowBase, int aRow, int aCol, int bRow, int bCol, int k0,
    float4& av0, float4& av1, float4& bv0, float4& bv1) {
    int gr = rowBase + aRow;
    av0 = make_float4(0.f, 0.f, 0.f, 0.f); av1 = av0;
    if (gr < M) {
        const float* ap = A + (size_t)gr * 128 + k0 + aCol;
        av0 = *(const float4*)(ap);
        av1 = *(const float4*)(ap + 4);
    }
    if (FUSE_BN) {
        int c = k0 + aCol;
        float4 sc0 = *(const float4*)&g_scale[c];
        float4 sc1 = *(const float4*)&g_scale[c + 4];
        float4 sh0 = *(const float4*)&g_shift[c];
        float4 sh1 = *(const float4*)&g_shift[c + 4];
        av0.x = fmaxf(fmaf(av0.x, sc0.x, sh0.x), 0.f);
        av0.y = fmaxf(fmaf(av0.y, sc0.y, sh0.y), 0.f);
        av0.z = fmaxf(fmaf(av0.z, sc0.z, sh0.z), 0.f);
        av0.w = fmaxf(fmaf(av0.w, sc0.w, sh0.w), 0.f);
        av1.x = fmaxf(fmaf(av1.x, sc1.x, sh1.x), 0.f);
        av1.y = fmaxf(fmaf(av1.y, sc1.y, sh1.y), 0.f);
        av1.z = fmaxf(fmaf(av1.z, sc1.z, sh1.z), 0.f);
        av1.w = fmaxf(fmaf(av1.w, sc1.w, sh1.w), 0.f);
    }
    const float* bp = B + (size_t)(k0 + bRow) * 128 + bCol;
    bv0 = *(const float4*)(bp);
    bv1 = *(const float4*)(bp + 4);
}

__device__ __forceinline__ void gemm_store_smem(
    uint32_t (*As)[AS_STRIDE], uint32_t (*Bs)[BS_STRIDE],
    int aRow, int aCol, int bRow, int bCol,
    const float4& av0, const float4& av1, const float4& bv0, const float4& bv1) {
    *(uint4*)&As[aRow][aCol]     = make_uint4(f2tf32(av0.x), f2tf32(av0.y), f2tf32(av0.z), f2tf32(av0.w));
    *(uint4*)&As[aRow][aCol + 4] = make_uint4(f2tf32(av1.x), f2tf32(av1.y), f2tf32(av1.z), f2tf32(av1.w));
    *(uint4*)&Bs[bRow][bCol]     = make_uint4(f2tf32(bv0.x), f2tf32(bv0.y), f2tf32(bv0.z), f2tf32(bv0.w));
    *(uint4*)&Bs[bRow][bCol + 4] = make_uint4(f2tf32(bv1.x), f2tf32(bv1.y), f2tf32(bv1.z), f2tf32(bv1.w));
}

template <bool FUSE_BN>
__global__ void __launch_bounds__(256, 2)
k_gemm(const float* __restrict__ A, const float* __restrict__ B,
       float* __restrict__ C, int M) {
    __shared__ uint32_t As[2][128][AS_STRIDE];   // [buf][m][k16]
    __shared__ uint32_t Bs[2][16][BS_STRIDE];    // [buf][k16][n]

    int tid = threadIdx.x;
    int lane = tid & 31;
    int warp = tid >> 5;
    int gid = lane >> 2;     // 0..7
    int tig = lane & 3;      // 0..3
    int wm = warp & 3;       // M warp 0..3
    int wn = warp >> 2;      // N warp 0..1
    int rowBase = blockIdx.x * 128;

    float acc[2][8][4];
#pragma unroll
    for (int i = 0; i < 2; i++)
#pragma unroll
        for (int j = 0; j < 8; j++)
#pragma unroll
            for (int q = 0; q < 4; q++) acc[i][j][q] = 0.f;

    int aRow = tid >> 1;               // 0..127
    int aCol = (tid & 1) * 8;          // 0 or 8
    int bRow = tid >> 4;               // 0..15
    int bCol = (tid & 15) * 8;         // 0..120

    float4 av0, av1, bv0, bv1;
    gemm_load_regs<FUSE_BN>(A, B, M, rowBase, aRow, aCol, bRow, bCol, 0, av0, av1, bv0, bv1);
    gemm_store_smem(As[0], Bs[0], aRow, aCol, bRow, bCol, av0, av1, bv0, bv1);
    __syncthreads();

#pragma unroll
    for (int c = 0; c < 8; c++) {
        int cur = c & 1;
        if (c < 7)
            gemm_load_regs<FUSE_BN>(A, B, M, rowBase, aRow, aCol, bRow, bCol,
                                    (c + 1) * 16, av0, av1, bv0, bv1);
#pragma unroll
        for (int ks = 0; ks < 16; ks += 8) {
            uint32_t a[2][4], b[8][2];
#pragma unroll
            for (int i = 0; i < 2; i++) {
                int mb = wm * 32 + i * 16;
                a[i][0] = As[cur][mb + gid][ks + tig];
                a[i][1] = As[cur][mb + gid + 8][ks + tig];
                a[i][2] = As[cur][mb + gid][ks + tig + 4];
                a[i][3] = As[cur][mb + gid + 8][ks + tig + 4];
            }
#pragma unroll
            for (int j = 0; j < 8; j++) {
                int nb = wn * 64 + j * 8;
                b[j][0] = Bs[cur][ks + tig][nb + gid];
                b[j][1] = Bs[cur][ks + tig + 4][nb + gid];
            }
#pragma unroll
            for (int i = 0; i < 2; i++)
#pragma unroll
                for (int j = 0; j < 8; j++) mma_tf32(acc[i][j], a[i], b[j]);
        }
        if (c < 7)
            gemm_store_smem(As[cur ^ 1], Bs[cur ^ 1], aRow, aCol, bRow, bCol, av0, av1, bv0, bv1);
        __syncthreads();
    }

    // epilogue
#pragma unroll
    for (int i = 0; i < 2; i++) {
        int r0 = rowBase + wm * 32 + i * 16 + gid;
        int r1 = r0 + 8;
#pragma unroll
        for (int j = 0; j < 8; j++) {
            int col = wn * 64 + j * 8 + tig * 2;
            if (r0 < M) *(float2*)(C + (size_t)r0 * 128 + col) = make_float2(acc[i][j][0], acc[i][j][1]);
            if (r1 < M) *(float2*)(C + (size_t)r1 * 128 + col) = make_float2(acc[i][j][2], acc[i][j][3]);
        }
    }
}

// ---------------- gather aggregation: warp per node --------------------------
// out[n] = dinv[n]*( h[n]*dinv[n] + sum_{s in in(n)} h[s]*dinv[s] ) + bias
// STATS: also accumulate per-column sum / sumsq of the output (BN input).
template <bool STATS>
__global__ void k_agg(const float* __restrict__ h, const float* __restrict__ bias,
                      float* __restrict__ out) {
    __shared__ float s_sum[8][DH];
    __shared__ float s_sq[8][DH];
    int warp = threadIdx.x >> 5;
    int lane = threadIdx.x & 31;
    int n = blockIdx.x * 8 + warp;
    float4 acc = make_float4(0.f, 0.f, 0.f, 0.f);
    if (n < NNODES) {
        float di = g_dinv[n];
        acc = ((const float4*)(h + (size_t)n * DH))[lane];
        acc.x *= di; acc.y *= di; acc.z *= di; acc.w *= di;
        int beg = g_start[n], end = g_start[n + 1];
        int s_next = (beg < end) ? g_src[beg] : 0;
        for (int idx = beg; idx < end; idx++) {
            int s = s_next;
            if (idx + 1 < end) s_next = g_src[idx + 1];
            float w = g_dinv[s];
            float4 v = ((const float4*)(h + (size_t)s * DH))[lane];
            acc.x = fmaf(v.x, w, acc.x);
            acc.y = fmaf(v.y, w, acc.y);
            acc.z = fmaf(v.z, w, acc.z);
            acc.w = fmaf(v.w, w, acc.w);
        }
        float4 bv = ((const float4*)bias)[lane];
        acc.x = fmaf(acc.x, di, bv.x);
        acc.y = fmaf(acc.y, di, bv.y);
        acc.z = fmaf(acc.z, di, bv.z);
        acc.w = fmaf(acc.w, di, bv.w);
        ((float4*)(out + (size_t)n * DH))[lane] = acc;
    }
    if (STATS) {
        int c = lane * 4;
        s_sum[warp][c + 0] = acc.x; s_sum[warp][c + 1] = acc.y;
        s_sum[warp][c + 2] = acc.z; s_sum[warp][c + 3] = acc.w;
        s_sq[warp][c + 0] = acc.x * acc.x; s_sq[warp][c + 1] = acc.y * acc.y;
        s_sq[warp][c + 2] = acc.z * acc.z; s_sq[warp][c + 3] = acc.w * acc.w;
        __syncthreads();
        int t = threadIdx.x;
        int rep = blockIdx.x & (NREP - 1);
        if (t < DH) {
            float s = 0.f;
#pragma unroll
            for (int w = 0; w < 8; w++) s += s_sum[w][t];
            atomicAdd(&g_colsum_r[rep][t], s);
        } else {
            int c2 = t - DH;
            float s = 0.f;
#pragma unroll
            for (int w = 0; w < 8; w++) s += s_sq[w][c2];
            atomicAdd(&g_colsq_r[rep][c2], s);
        }
    }
}

// ---------------- BN stats: reduce replicas -> scale/shift --------------------
__global__ void k_bnstats(const float* __restrict__ gamma, const float* __restrict__ beta) {
    int t = threadIdx.x;
    float sum = 0.f, sq = 0.f;
#pragma unroll
    for (int r = 0; r < NREP; r++) { sum += g_colsum_r[r][t]; sq += g_colsq_r[r][t]; }
    float mean = sum * (1.0f / NNODES);
    float var = sq * (1.0f / NNODES) - mean * mean;
    float inv = rsqrtf(var + 1e-5f);
    float sc = gamma[t] * inv;
    g_scale[t] = sc;
    g_shift[t] = beta[t] - mean * sc;
}

// ---------------- launch -----------------------------------------------------
extern "C" void kernel_launch(void* const* d_in, const int* in_sizes, int n_in,
                              void* d_out, int out_size) {
    const float* x     = (const float*)d_in[0];
    const int*   ei    = (const int*)d_in[1];
    const float* W1    = (const float*)d_in[2];
    const float* b1    = (const float*)d_in[3];
    const float* gamma = (const float*)d_in[4];
    const float* beta  = (const float*)d_in[5];
    const float* W2    = (const float*)d_in[6];
    const float* b2    = (const float*)d_in[7];
    float*       out   = (float*)d_out;

    float* h   = nullptr; cudaGetSymbolAddress((void**)&h,   g_h);
    float* agg = nullptr; cudaGetSymbolAddress((void**)&agg, g_agg);

    // side stream + fork/join events (created once; host-side only — the
    // captured graph holds the dependencies, so replays are identical)
    static cudaStream_t s2 = nullptr;
    static cudaEvent_t ev_fork = nullptr, ev_join = nullptr;
    if (s2 == nullptr) {
        cudaStreamCreateWithFlags(&s2, cudaStreamNonBlocking);
        cudaEventCreateWithFlags(&ev_fork, cudaEventDisableTiming);
        cudaEventCreateWithFlags(&ev_join, cudaEventDisableTiming);
    }

    // fork: CSR build (depends only on edge_index) runs concurrently with GEMM1
    cudaEventRecord(ev_fork, 0);
    cudaStreamWaitEvent(s2, ev_fork, 0);

    k_init<<<(NNODES + 255) / 256, 256, 0, s2>>>();
    k_count<<<(NEDGES / 4 + 255) / 256, 256, 0, s2>>>(ei);
    k_scan1<<<NSCAN_BLOCKS, SCAN_CHUNK, 0, s2>>>();
    k_scan3<<<(NNODES + 255) / 256, 256, 0, s2>>>();
    k_buildcsr<<<(NEDGES + 255) / 256, 256, 0, s2>>>(ei);

    k_gemm<false><<<(NNODES + 127) / 128, 256>>>(x, W1, h, NNODES);

    // join
    cudaEventRecord(ev_join, s2);
    cudaStreamWaitEvent(0, ev_join, 0);

    // layer 1: aggregate(+colstats) -> BN params
    k_agg<true><<<(NNODES + 7) / 8, 256>>>(h, b1, agg);
    k_bnstats<<<1, DH>>>(gamma, beta);

    // layer 2: GEMM(tf32, fused BN+ReLU on A) -> aggregate -> d_out
    k_gemm<true><<<(NNODES + 127) / 128, 256>>>(agg, W2, h, NNODES);
    k_agg<false><<<(NNODES + 7) / 8, 256>>>(h, b2, out);
}

// round 7
// speedup vs baseline: 3.5301x; 1.1613x over previous
#include <cuda_runtime.h>
#include <cuda_fp16.h>
#include <cstdint>

#define NNODES 100000
#define NEDGES 600000
#define DH 128
#define SCAN_CHUNK 1024
#define NSCAN_BLOCKS ((NNODES + SCAN_CHUNK - 1) / SCAN_CHUNK)   // 98
#define NREP 32   // replicated column-stat accumulators

// ---------------- scratch (static device memory; no allocations) -------------
__device__ __half g_h[(size_t)NNODES * DH];    // 25.6 MB (fp16 features)
__device__ float  g_agg[(size_t)NNODES * DH];  // 51.2 MB (BN input, fp32)
__device__ float  g_dinv[NNODES];
__device__ int    g_deg[NNODES];
__device__ int    g_start[NNODES + 1];
__device__ int    g_cursor[NNODES];
__device__ int    g_src[NEDGES];
__device__ int    g_blocksums[NSCAN_BLOCKS];
__device__ float  g_colsum_r[NREP][DH];
__device__ float  g_colsq_r[NREP][DH];
__device__ float  g_scale[DH];
__device__ float  g_shift[DH];

// ---------------- helpers ----------------------------------------------------
__device__ __forceinline__ uint32_t f2tf32(float f) {
    uint32_t r;
    asm("cvt.rna.tf32.f32 %0, %1;" : "=r"(r) : "f"(f));
    return r;
}

__device__ __forceinline__ void mma_tf32(float* c, const uint32_t* a, const uint32_t* b) {
    asm volatile("mma.sync.aligned.m16n8k8.row.col.f32.tf32.tf32.f32 "
        "{%0,%1,%2,%3}, {%4,%5,%6,%7}, {%8,%9}, {%0,%1,%2,%3};"
        : "+f"(c[0]), "+f"(c[1]), "+f"(c[2]), "+f"(c[3])
        : "r"(a[0]), "r"(a[1]), "r"(a[2]), "r"(a[3]), "r"(b[0]), "r"(b[1]));
}

// ---------------- init: zero deg + replicated column stats --------------------
__global__ void k_init() {
    int i = blockIdx.x * blockDim.x + threadIdx.x;
    if (i < NNODES) g_deg[i] = 0;
    if (i < NREP * DH) {
        ((float*)g_colsum_r)[i] = 0.f;
        ((float*)g_colsq_r)[i] = 0.f;
    }
}

// ---------------- count incoming degree (dst side) ----------------------------
__global__ void k_count(const int* __restrict__ ei) {
    int e4 = blockIdx.x * blockDim.x + threadIdx.x;
    if (e4 * 4 >= NEDGES) return;
    int4 d = ((const int4*)(ei + NEDGES))[e4];
    atomicAdd(&g_deg[d.x], 1);
    atomicAdd(&g_deg[d.y], 1);
    atomicAdd(&g_deg[d.z], 1);
    atomicAdd(&g_deg[d.w], 1);
}

// ---------------- block-wise scan of deg (per 1024-chunk) --------------------
__global__ void k_scan1() {
    __shared__ int s[SCAN_CHUNK];
    int i = blockIdx.x * SCAN_CHUNK + threadIdx.x;
    int v = (i < NNODES) ? g_deg[i] : 0;
    s[threadIdx.x] = v;
    __syncthreads();
    for (int off = 1; off < SCAN_CHUNK; off <<= 1) {
        int t = (threadIdx.x >= off) ? s[threadIdx.x - off] : 0;
        __syncthreads();
        s[threadIdx.x] += t;
        __syncthreads();
    }
    if (i < NNODES) g_start[i] = s[threadIdx.x] - v;   // exclusive within chunk
    if (threadIdx.x == SCAN_CHUNK - 1) g_blocksums[blockIdx.x] = s[SCAN_CHUNK - 1];
}

// ---------------- finalize offsets: chunk-sum scan done in-block --------------
__global__ void k_scan3() {
    __shared__ int excl[128];
    int t = threadIdx.x;
    if (t < 128) {
        int v = (t < NSCAN_BLOCKS) ? g_blocksums[t] : 0;
        excl[t] = v;
    }
    __syncthreads();
    if (t < 128) {
        for (int off = 1; off < 128; off <<= 1) {
            int u = (t >= off) ? excl[t - off] : 0;
            __syncthreads();
            excl[t] += u;
            __syncthreads();
        }
        int v = (t < NSCAN_BLOCKS) ? g_blocksums[t] : 0;
        excl[t] -= v;   // exclusive
    } else {
        for (int off = 1; off < 128; off <<= 1) { __syncthreads(); __syncthreads(); }
    }
    __syncthreads();
    int i = blockIdx.x * blockDim.x + t;
    if (i < NNODES) {
        int st = g_start[i] + excl[i >> 10];
        g_start[i] = st;
        g_cursor[i] = st;
        g_dinv[i] = rsqrtf((float)(g_deg[i] + 1));
    }
    if (i == 0) g_start[NNODES] = NEDGES;
}

// ---------------- scatter edges into CSR (by dst) ----------------------------
__global__ void k_buildcsr(const int* __restrict__ ei) {
    int e = blockIdx.x * blockDim.x + threadIdx.x;
    if (e >= NEDGES) return;
    int src = ei[e];
    int dst = ei[NEDGES + e];
    int pos = atomicAdd(&g_cursor[dst], 1);
    g_src[pos] = src;
}

// ---------------- TF32 tensor-core GEMM: C[M,128](fp16) = A @ B --------------
// 128x128 block tile, 256 threads = 8 warps in 4(M)x2(N); warp tile 32x64.
// Double-buffered smem pipeline. FUSE_BN: y = relu(a*scale+shift) on A load.
#define AS_STRIDE 20
#define BS_STRIDE 136

template <bool FUSE_BN>
__device__ __forceinline__ void gemm_load_regs(
    const float* __restrict__ A, const float* __restrict__ B, int M,
    int rowBase, int aRow, int aCol, int bRow, int bCol, int k0,
    float4& av0, float4& av1, float4& bv0, float4& bv1) {
    int gr = rowBase + aRow;
    av0 = make_float4(0.f, 0.f, 0.f, 0.f); av1 = av0;
    if (gr < M) {
        const float* ap = A + (size_t)gr * 128 + k0 + aCol;
        av0 = *(const float4*)(ap);
        av1 = *(const float4*)(ap + 4);
    }
    if (FUSE_BN) {
        int c = k0 + aCol;
        float4 sc0 = *(const float4*)&g_scale[c];
        float4 sc1 = *(const float4*)&g_scale[c + 4];
        float4 sh0 = *(const float4*)&g_shift[c];
        float4 sh1 = *(const float4*)&g_shift[c + 4];
        av0.x = fmaxf(fmaf(av0.x, sc0.x, sh0.x), 0.f);
        av0.y = fmaxf(fmaf(av0.y, sc0.y, sh0.y), 0.f);
        av0.z = fmaxf(fmaf(av0.z, sc0.z, sh0.z), 0.f);
        av0.w = fmaxf(fmaf(av0.w, sc0.w, sh0.w), 0.f);
        av1.x = fmaxf(fmaf(av1.x, sc1.x, sh1.x), 0.f);
        av1.y = fmaxf(fmaf(av1.y, sc1.y, sh1.y), 0.f);
        av1.z = fmaxf(fmaf(av1.z, sc1.z, sh1.z), 0.f);
        av1.w = fmaxf(fmaf(av1.w, sc1.w, sh1.w), 0.f);
    }
    const float* bp = B + (size_t)(k0 + bRow) * 128 + bCol;
    bv0 = *(const float4*)(bp);
    bv1 = *(const float4*)(bp + 4);
}

__device__ __forceinline__ void gemm_store_smem(
    uint32_t (*As)[AS_STRIDE], uint32_t (*Bs)[BS_STRIDE],
    int aRow, int aCol, int bRow, int bCol,
    const float4& av0, const float4& av1, const float4& bv0, const float4& bv1) {
    *(uint4*)&As[aRow][aCol]     = make_uint4(f2tf32(av0.x), f2tf32(av0.y), f2tf32(av0.z), f2tf32(av0.w));
    *(uint4*)&As[aRow][aCol + 4] = make_uint4(f2tf32(av1.x), f2tf32(av1.y), f2tf32(av1.z), f2tf32(av1.w));
    *(uint4*)&Bs[bRow][bCol]     = make_uint4(f2tf32(bv0.x), f2tf32(bv0.y), f2tf32(bv0.z), f2tf32(bv0.w));
    *(uint4*)&Bs[bRow][bCol + 4] = make_uint4(f2tf32(bv1.x), f2tf32(bv1.y), f2tf32(bv1.z), f2tf32(bv1.w));
}

template <bool FUSE_BN>
__global__ void __launch_bounds__(256, 2)
k_gemm(const float* __restrict__ A, const float* __restrict__ B,
       __half* __restrict__ C, int M) {
    __shared__ uint32_t As[2][128][AS_STRIDE];   // [buf][m][k16]
    __shared__ uint32_t Bs[2][16][BS_STRIDE];    // [buf][k16][n]

    int tid = threadIdx.x;
    int lane = tid & 31;
    int warp = tid >> 5;
    int gid = lane >> 2;     // 0..7
    int tig = lane & 3;      // 0..3
    int wm = warp & 3;       // M warp 0..3
    int wn = warp >> 2;      // N warp 0..1
    int rowBase = blockIdx.x * 128;

    float acc[2][8][4];
#pragma unroll
    for (int i = 0; i < 2; i++)
#pragma unroll
        for (int j = 0; j < 8; j++)
#pragma unroll
            for (int q = 0; q < 4; q++) acc[i][j][q] = 0.f;

    int aRow = tid >> 1;               // 0..127
    int aCol = (tid & 1) * 8;          // 0 or 8
    int bRow = tid >> 4;               // 0..15
    int bCol = (tid & 15) * 8;         // 0..120

    float4 av0, av1, bv0, bv1;
    gemm_load_regs<FUSE_BN>(A, B, M, rowBase, aRow, aCol, bRow, bCol, 0, av0, av1, bv0, bv1);
    gemm_store_smem(As[0], Bs[0], aRow, aCol, bRow, bCol, av0, av1, bv0, bv1);
    __syncthreads();

#pragma unroll
    for (int c = 0; c < 8; c++) {
        int cur = c & 1;
        if (c < 7)
            gemm_load_regs<FUSE_BN>(A, B, M, rowBase, aRow, aCol, bRow, bCol,
                                    (c + 1) * 16, av0, av1, bv0, bv1);
#pragma unroll
        for (int ks = 0; ks < 16; ks += 8) {
            uint32_t a[2][4], b[8][2];
#pragma unroll
            for (int i = 0; i < 2; i++) {
                int mb = wm * 32 + i * 16;
                a[i][0] = As[cur][mb + gid][ks + tig];
                a[i][1] = As[cur][mb + gid + 8][ks + tig];
                a[i][2] = As[cur][mb + gid][ks + tig + 4];
                a[i][3] = As[cur][mb + gid + 8][ks + tig + 4];
            }
#pragma unroll
            for (int j = 0; j < 8; j++) {
                int nb = wn * 64 + j * 8;
                b[j][0] = Bs[cur][ks + tig][nb + gid];
                b[j][1] = Bs[cur][ks + tig + 4][nb + gid];
            }
#pragma unroll
            for (int i = 0; i < 2; i++)
#pragma unroll
                for (int j = 0; j < 8; j++) mma_tf32(acc[i][j], a[i], b[j]);
        }
        if (c < 7)
            gemm_store_smem(As[cur ^ 1], Bs[cur ^ 1], aRow, aCol, bRow, bCol, av0, av1, bv0, bv1);
        __syncthreads();
    }

    // epilogue: fp32 acc -> fp16 store
#pragma unroll
    for (int i = 0; i < 2; i++) {
        int r0 = rowBase + wm * 32 + i * 16 + gid;
        int r1 = r0 + 8;
#pragma unroll
        for (int j = 0; j < 8; j++) {
            int col = wn * 64 + j * 8 + tig * 2;
            if (r0 < M) *(__half2*)(C + (size_t)r0 * 128 + col) =
                __floats2half2_rn(acc[i][j][0], acc[i][j][1]);
            if (r1 < M) *(__half2*)(C + (size_t)r1 * 128 + col) =
                __floats2half2_rn(acc[i][j][2], acc[i][j][3]);
        }
    }
}

// ---------------- gather aggregation (fp16 features): warp per node ----------
// out[n] = dinv[n]*( h[n]*dinv[n] + sum_{s in in(n)} h[s]*dinv[s] ) + bias
// Lane handles 4 columns (8 bytes fp16). Edge loop unrolled x2 for MLP.
template <bool STATS>
__global__ void k_agg(const __half* __restrict__ h, const float* __restrict__ bias,
                      float* __restrict__ out) {
    __shared__ float s_sum[8][DH];
    __shared__ float s_sq[8][DH];
    int warp = threadIdx.x >> 5;
    int lane = threadIdx.x & 31;
    int n = blockIdx.x * 8 + warp;
    float4 acc = make_float4(0.f, 0.f, 0.f, 0.f);
    if (n < NNODES) {
        float di = g_dinv[n];
        {
            uint2 u = ((const uint2*)(h + (size_t)n * DH))[lane];
            float2 fa = __half22float2(*(__half2*)&u.x);
            float2 fb = __half22float2(*(__half2*)&u.y);
            acc.x = fa.x * di; acc.y = fa.y * di;
            acc.z = fb.x * di; acc.w = fb.y * di;
        }
        int beg = g_start[n], end = g_start[n + 1];
        int idx = beg;
        for (; idx + 2 <= end; idx += 2) {
            int s0 = g_src[idx], s1 = g_src[idx + 1];
            float w0 = g_dinv[s0], w1 = g_dinv[s1];
            uint2 u0 = ((const uint2*)(h + (size_t)s0 * DH))[lane];
            uint2 u1 = ((const uint2*)(h + (size_t)s1 * DH))[lane];
            float2 a0 = __half22float2(*(__half2*)&u0.x);
            float2 b0 = __half22float2(*(__half2*)&u0.y);
            float2 a1 = __half22float2(*(__half2*)&u1.x);
            float2 b1 = __half22float2(*(__half2*)&u1.y);
            acc.x = fmaf(a0.x, w0, acc.x); acc.y = fmaf(a0.y, w0, acc.y);
            acc.z = fmaf(b0.x, w0, acc.z); acc.w = fmaf(b0.y, w0, acc.w);
            acc.x = fmaf(a1.x, w1, acc.x); acc.y = fmaf(a1.y, w1, acc.y);
            acc.z = fmaf(b1.x, w1, acc.z); acc.w = fmaf(b1.y, w1, acc.w);
        }
        if (idx < end) {
            int s0 = g_src[idx];
            float w0 = g_dinv[s0];
            uint2 u0 = ((const uint2*)(h + (size_t)s0 * DH))[lane];
            float2 a0 = __half22float2(*(__half2*)&u0.x);
            float2 b0 = __half22float2(*(__half2*)&u0.y);
            acc.x = fmaf(a0.x, w0, acc.x); acc.y = fmaf(a0.y, w0, acc.y);
            acc.z = fmaf(b0.x, w0, acc.z); acc.w = fmaf(b0.y, w0, acc.w);
        }
        float4 bv = ((const float4*)bias)[lane];
        acc.x = fmaf(acc.x, di, bv.x);
        acc.y = fmaf(acc.y, di, bv.y);
        acc.z = fmaf(acc.z, di, bv.z);
        acc.w = fmaf(acc.w, di, bv.w);
        ((float4*)(out + (size_t)n * DH))[lane] = acc;
    }
    if (STATS) {
        int c = lane * 4;
        s_sum[warp][c + 0] = acc.x; s_sum[warp][c + 1] = acc.y;
        s_sum[warp][c + 2] = acc.z; s_sum[warp][c + 3] = acc.w;
        s_sq[warp][c + 0] = acc.x * acc.x; s_sq[warp][c + 1] = acc.y * acc.y;
        s_sq[warp][c + 2] = acc.z * acc.z; s_sq[warp][c + 3] = acc.w * acc.w;
        __syncthreads();
        int t = threadIdx.x;
        int rep = blockIdx.x & (NREP - 1);
        if (t < DH) {
            float s = 0.f;
#pragma unroll
            for (int w = 0; w < 8; w++) s += s_sum[w][t];
            atomicAdd(&g_colsum_r[rep][t], s);
        } else {
            int c2 = t - DH;
            float s = 0.f;
#pragma unroll
            for (int w = 0; w < 8; w++) s += s_sq[w][c2];
            atomicAdd(&g_colsq_r[rep][c2], s);
        }
    }
}

// ---------------- final aggregation writes fp32 out (no fp16 on last layer) --
// (same kernel: out is float*, h is fp16 — fits both layers)

// ---------------- BN stats: reduce replicas -> scale/shift --------------------
__global__ void k_bnstats(const float* __restrict__ gamma, const float* __restrict__ beta) {
    int t = threadIdx.x;
    float sum = 0.f, sq = 0.f;
#pragma unroll
    for (int r = 0; r < NREP; r++) { sum += g_colsum_r[r][t]; sq += g_colsq_r[r][t]; }
    float mean = sum * (1.0f / NNODES);
    float var = sq * (1.0f / NNODES) - mean * mean;
    float inv = rsqrtf(var + 1e-5f);
    float sc = gamma[t] * inv;
    g_scale[t] = sc;
    g_shift[t] = beta[t] - mean * sc;
}

// ---------------- launch -----------------------------------------------------
extern "C" void kernel_launch(void* const* d_in, const int* in_sizes, int n_in,
                              void* d_out, int out_size) {
    const float* x     = (const float*)d_in[0];
    const int*   ei    = (const int*)d_in[1];
    const float* W1    = (const float*)d_in[2];
    const float* b1    = (const float*)d_in[3];
    const float* gamma = (const float*)d_in[4];
    const float* beta  = (const float*)d_in[5];
    const float* W2    = (const float*)d_in[6];
    const float* b2    = (const float*)d_in[7];
    float*       out   = (float*)d_out;

    __half* h  = nullptr; cudaGetSymbolAddress((void**)&h,   g_h);
    float* agg = nullptr; cudaGetSymbolAddress((void**)&agg, g_agg);

    static cudaStream_t s2 = nullptr;
    static cudaEvent_t ev_fork = nullptr, ev_join = nullptr;
    if (s2 == nullptr) {
        cudaStreamCreateWithFlags(&s2, cudaStreamNonBlocking);
        cudaEventCreateWithFlags(&ev_fork, cudaEventDisableTiming);
        cudaEventCreateWithFlags(&ev_join, cudaEventDisableTiming);
    }

    // fork: CSR build (depends only on edge_index) concurrent with GEMM1
    cudaEventRecord(ev_fork, 0);
    cudaStreamWaitEvent(s2, ev_fork, 0);

    k_init<<<(NNODES + 255) / 256, 256, 0, s2>>>();
    k_count<<<(NEDGES / 4 + 255) / 256, 256, 0, s2>>>(ei);
    k_scan1<<<NSCAN_BLOCKS, SCAN_CHUNK, 0, s2>>>();
    k_scan3<<<(NNODES + 255) / 256, 256, 0, s2>>>();
    k_buildcsr<<<(NEDGES + 255) / 256, 256, 0, s2>>>(ei);

    k_gemm<false><<<(NNODES + 127) / 128, 256>>>(x, W1, h, NNODES);

    cudaEventRecord(ev_join, s2);
    cudaStreamWaitEvent(0, ev_join, 0);

    // layer 1: aggregate(+colstats) -> BN params
    k_agg<true><<<(NNODES + 7) / 8, 256>>>(h, b1, agg);
    k_bnstats<<<1, DH>>>(gamma, beta);

    // layer 2: GEMM(tf32, fused BN+ReLU on A) -> aggregate -> d_out
    k_gemm<true><<<(NNODES + 127) / 128, 256>>>(agg, W2, h, NNODES);
    k_agg<false><<<(NNODES + 7) / 8, 256>>>(h, b2, out);
}